// round 10
// baseline (speedup 1.0000x reference)
#include <cuda_runtime.h>
#include <cuda_bf16.h>

// SpatialConsistencyLoss — one-wave persistent fused kernel.
//   original, enhanced: [32,3,512,512] f32
//   p = avg_pool4(mean_c(orig)) - avg_pool4(mean_c(enh))   [32,128,128]
//   loss[i,j] = sum_dirs (p[i,j] - p[nbr])^2, zero-padded  -> [32,1,128,128]
//
// 148 blocks x 1024 threads: <= SM count (148 B300 / 152 GB300) so ALL
// blocks are wave-1 resident -> counter grid-barrier is deadlock-free.
// 4096 pooled rows split flat (100 blocks x 28 + 48 x 27, 1.2% imbalance).
// Phase 1 streams the inputs exactly once (201 MB, the DRAM minimum) into
// smem; only each strip's first/last row goes to global scratch (151 KB,
// L2-hot at phase-2 read). Phase 2 computes the loss from smem + 2 halo
// rows. Sync cost: one fence+atomic per block (148 total).

#define B 32
#define HP 128
#define WP 128
#define HIN 512
#define WIN 512
#define CH_STRIDE (HIN * WIN)          // 262144
#define IMG_STRIDE (3 * CH_STRIDE)     // 786432
#define THREADS 1024
#define NBLOCKS 148
#define TOTAL_ROWS (B * HP)            // 4096
#define ROWS_BASE (TOTAL_ROWS / NBLOCKS)             // 27
#define BIG_BLOCKS (TOTAL_ROWS - ROWS_BASE * NBLOCKS) // 100 blocks get 28
#define MAX_ROWS (ROWS_BASE + 1)       // 28

__device__ float g_rows[TOTAL_ROWS * WP];   // boundary-row scratch (2 MB, ~151KB used)
__device__ unsigned int g_arrive = 0;
__device__ unsigned int g_exit   = 0;

__device__ __forceinline__ float sq(float x) { return x * x; }

__global__ __launch_bounds__(THREADS, 1)
void scl_onewave_kernel(const float* __restrict__ orig,
                        const float* __restrict__ enh,
                        float* __restrict__ out) {
    const int k = blockIdx.x;
    int start, nrows;
    if (k < BIG_BLOCKS) { start = k * MAX_ROWS; nrows = MAX_ROWS; }
    else { start = BIG_BLOCKS * MAX_ROWS + (k - BIG_BLOCKS) * ROWS_BASE; nrows = ROWS_BASE; }

    __shared__ __align__(16) float sp[MAX_ROWS * WP];   // 28*128*4 = 14 KB

    const int nitems = nrows << 7;

    // ---- Phase 1: pooled diff rows [start, start+nrows) ----
    // One pooled pixel per item: 24 warp-contiguous LDG.128 (512B/warp/load).
    for (int it = threadIdx.x; it < nitems; it += THREADS) {
        int r   = it >> 7;
        int col = it & (WP - 1);
        int gr  = start + r;               // global row = b*128 + i
        int b   = gr >> 7;
        int i   = gr & (HP - 1);

        int base0 = b * IMG_STRIDE + (i * 4) * WIN + col * 4;
        float s = 0.0f;
#pragma unroll
        for (int c = 0; c < 3; ++c) {
            int base = base0 + c * CH_STRIDE;
#pragma unroll
            for (int rr = 0; rr < 4; ++rr) {
                float4 ov = *reinterpret_cast<const float4*>(orig + base + rr * WIN);
                float4 ev = *reinterpret_cast<const float4*>(enh  + base + rr * WIN);
                s += (ov.x - ev.x) + (ov.y - ev.y) + (ov.z - ev.z) + (ov.w - ev.w);
            }
        }
        float v = s * (1.0f / 48.0f);      // /3 channels, /16 pool
        sp[it] = v;
        // Publish only rows a neighboring block will read.
        if (r == 0 || r == nrows - 1)
            g_rows[(gr << 7) + col] = v;
    }

    // ---- Grid barrier (all 148 blocks wave-1 resident; self-resetting) ----
    __syncthreads();
    if (threadIdx.x == 0) {
        __threadfence();                    // release boundary-row stores
        atomicAdd(&g_arrive, 1u);
        while (*(volatile unsigned int*)&g_arrive < NBLOCKS) { }
        __threadfence();                    // acquire neighbors' stores
    }
    __syncthreads();

    // ---- Phase 2: loss for the same rows (smem + 2 L2-hot halo rows) ----
    for (int it = threadIdx.x; it < nitems; it += THREADS) {
        int r   = it >> 7;
        int col = it & (WP - 1);
        int gr  = start + r;
        int i   = gr & (HP - 1);

        float c = sp[it];

        float up;
        if (i == 0)              up = 0.0f;                       // image top
        else if (r > 0)          up = sp[it - WP];
        else                     up = g_rows[((gr - 1) << 7) + col];

        float dn;
        if (i == HP - 1)         dn = 0.0f;                       // image bottom
        else if (r < nrows - 1)  dn = sp[it + WP];
        else                     dn = g_rows[((gr + 1) << 7) + col];

        float left  = (col > 0)      ? sp[it - 1] : 0.0f;
        float right = (col < WP - 1) ? sp[it + 1] : 0.0f;

        out[(gr << 7) + col] =
            sq(c - left) + sq(c - right) + sq(c - up) + sq(c - dn);
    }

    // ---- Reset barrier counters for the next graph replay ----
    __syncthreads();
    if (threadIdx.x == 0) {
        unsigned int old = atomicAdd(&g_exit, 1u);
        if (old == NBLOCKS - 1) {
            atomicExch(&g_arrive, 0u);
            atomicExch(&g_exit, 0u);
        }
    }
}

extern "C" void kernel_launch(void* const* d_in, const int* in_sizes, int n_in,
                              void* d_out, int out_size) {
    const float* orig = (const float*)d_in[0];
    const float* enh  = (const float*)d_in[1];
    float* out = (float*)d_out;

    scl_onewave_kernel<<<NBLOCKS, THREADS>>>(orig, enh, out);
}

// round 11
// speedup vs baseline: 1.0451x; 1.0451x over previous
#include <cuda_runtime.h>
#include <cuda_bf16.h>

// SpatialConsistencyLoss — two kernels; input stream uses evict-first loads
// so the 2 MB pooled scratch survives in L2 for the loss pass.
//   original, enhanced: [32,3,512,512] f32
//   p = avg_pool4(mean_c(orig)) - avg_pool4(mean_c(enh))   [32,128,128]
//   loss[i,j] = sum_dirs (p[i,j] - p[nbr])^2, zero-padded  -> [32,1,128,128]
//
// Evidence basis: R9 profile showed the loss kernel reading the full 2 MB
// scratch from DRAM at 369 GB/s effective (shared-line MSHR serialization)
// => 5.5us for ~1us of work. The input stream is read-once, so __ldcs
// (evict-first) keeps it from evicting the scratch; loss reads become
// L2 hits. Pool body is the proven 6.4 TB/s streaming structure.

#define B 32
#define HP 128
#define WP 128
#define NPOOL (B * HP * WP)   // 524288
#define HIN 512
#define WIN 512
#define CH_STRIDE (HIN * WIN)          // 262144
#define IMG_STRIDE (3 * CH_STRIDE)     // 786432

__device__ float g_pooled[NPOOL];   // 2 MB scratch

__device__ __forceinline__ float sq(float x) { return x * x; }

__global__ void pool_diff_kernel(const float* __restrict__ orig,
                                 const float* __restrict__ enh) {
    int idx = blockIdx.x * blockDim.x + threadIdx.x;

    int j = idx & (WP - 1);
    int i = (idx >> 7) & (HP - 1);
    int b = idx >> 14;

    int base0 = b * IMG_STRIDE + (i * 4) * WIN + (j * 4);

    float s = 0.0f;
#pragma unroll
    for (int c = 0; c < 3; ++c) {
        int base = base0 + c * CH_STRIDE;
#pragma unroll
        for (int r = 0; r < 4; ++r) {
            // Evict-first streaming loads: read-once data, keep L2 for scratch.
            float4 ov = __ldcs(reinterpret_cast<const float4*>(orig + base + r * WIN));
            float4 ev = __ldcs(reinterpret_cast<const float4*>(enh  + base + r * WIN));
            s += (ov.x - ev.x) + (ov.y - ev.y) + (ov.z - ev.z) + (ov.w - ev.w);
        }
    }
    g_pooled[idx] = s * (1.0f / 48.0f);   // /3 channels, /16 pool
}

// One thread = 4 adjacent output pixels (one float4 along j).
__global__ void loss_kernel_v4(float* __restrict__ out) {
    int t = blockIdx.x * blockDim.x + threadIdx.x;   // 0 .. NPOOL/4 - 1

    int j4  = (t & 31) << 2;      // 0,4,...,124 : first j of the quad
    int row = t >> 5;             // b*128 + i
    int i   = row & (HP - 1);
    int base = (row << 7) + j4;

    const float4* p4 = reinterpret_cast<const float4*>(g_pooled);
    float4 c  = p4[base >> 2];
    float4 up = (i > 0)      ? p4[(base - WP) >> 2] : make_float4(0.f, 0.f, 0.f, 0.f);
    float4 dn = (i < HP - 1) ? p4[(base + WP) >> 2] : make_float4(0.f, 0.f, 0.f, 0.f);
    float left  = (j4 > 0)      ? g_pooled[base - 1] : 0.f;
    float right = (j4 < WP - 4) ? g_pooled[base + 4] : 0.f;

    float4 o;
    o.x = sq(c.x - left) + sq(c.x - c.y)   + sq(c.x - up.x) + sq(c.x - dn.x);
    o.y = sq(c.y - c.x)  + sq(c.y - c.z)   + sq(c.y - up.y) + sq(c.y - dn.y);
    o.z = sq(c.z - c.y)  + sq(c.z - c.w)   + sq(c.z - up.z) + sq(c.z - dn.z);
    o.w = sq(c.w - c.z)  + sq(c.w - right) + sq(c.w - up.w) + sq(c.w - dn.w);

    reinterpret_cast<float4*>(out)[base >> 2] = o;
}

extern "C" void kernel_launch(void* const* d_in, const int* in_sizes, int n_in,
                              void* d_out, int out_size) {
    const float* orig = (const float*)d_in[0];
    const float* enh  = (const float*)d_in[1];
    float* out = (float*)d_out;

    const int threads = 256;

    pool_diff_kernel<<<NPOOL / threads, threads>>>(orig, enh);
    loss_kernel_v4<<<NPOOL / 4 / threads, threads>>>(out);
}